// round 1
// baseline (speedup 1.0000x reference)
#include <cuda_runtime.h>

#define NDET 8192
#define ROW  85
#define IMG  640

// Scratch (allocation-free rule: __device__ globals). All fully rewritten
// every launch -> deterministic across graph replays.
__device__ float  g_conf[NDET];
__device__ float4 g_box[NDET];
__device__ int    g_valid[NDET];
__device__ float  c_conf[NDET];
__device__ float4 c_box[NDET];
__device__ float  s_conf[NDET];
__device__ float4 s_box[NDET];

// Kernel 1: one warp per detection. Coalesced loads of the 85-float row,
// warp max-reduce over classes 6..84, compute clamped xyxy + validity.
// Also zeros the 40960-float output (poisoned to 0xAA by harness).
__global__ void __launch_bounds__(256) prep_kernel(const float* __restrict__ x,
                                                   float* __restrict__ out) {
    int gtid = blockIdx.x * blockDim.x + threadIdx.x;
    if (gtid < NDET * 5) out[gtid] = 0.0f;   // boxes (4*N) + scores (N)

    int det  = gtid >> 5;
    int lane = gtid & 31;
    if (det >= NDET) return;

    const float* row = x + (long)det * ROW;
    float v0 = row[lane];                                  // positions 0..31
    float v1 = row[lane + 32];                             // positions 32..63
    float v2 = (lane < 21) ? row[lane + 64] : -1e30f;      // positions 64..84

    // max over class scores at positions 6..84 (class ids 1..79)
    float m = (lane >= 6) ? v0 : -1e30f;
    m = fmaxf(m, v1);
    m = fmaxf(m, v2);
    #pragma unroll
    for (int o = 16; o; o >>= 1)
        m = fmaxf(m, __shfl_xor_sync(0xffffffffu, m, o));

    float b0   = __shfl_sync(0xffffffffu, v0, 0);
    float b1   = __shfl_sync(0xffffffffu, v0, 1);
    float b2   = __shfl_sync(0xffffffffu, v0, 2);
    float b3   = __shfl_sync(0xffffffffu, v0, 3);
    float conf = __shfl_sync(0xffffffffu, v0, 4);
    float cls0 = __shfl_sync(0xffffffffu, v0, 5);   // class id 0 score

    if (lane == 0) {
        float cx = b0 * 640.0f, cy = b1 * 640.0f;
        float w  = b2 * 640.0f, h  = b3 * 640.0f;
        // argmax==0  <=>  no later class strictly greater than cls0
        int valid = (conf > 0.25f) && (cls0 >= m) && ((w > 0.0f) || (h > 0.0f));

        float hw = truncf(w * 0.5f);   // == jnp.trunc(w/2): /2 is exact
        float hh = truncf(h * 0.5f);
        // float->int cast truncates toward zero, matching .astype(int32)
        int x1 = (int)(cx - hw);
        int y1 = (int)(cy - hh);
        int x2 = (int)(cx + hw);
        int y2 = (int)(cy + hh);
        x1 = x1 > 0 ? x1 : 0;
        y1 = y1 > 0 ? y1 : 0;
        x2 = x2 < IMG ? x2 : IMG;
        y2 = y2 < IMG ? y2 : IMG;

        g_valid[det] = valid;
        g_conf[det]  = conf;
        g_box[det]   = make_float4((float)x1, (float)y1, (float)x2, (float)y2);
    }
}

// Kernel 2: single block. Ordered compaction (shared-mem scan), stable
// rank-sort by (conf desc, original index asc), greedy sequential NMS with
// parallel inner suppression, scatter of survivors into sorted rank slots.
__global__ void __launch_bounds__(1024) nms_kernel(float* __restrict__ out) {
    const int t = threadIdx.x;
    __shared__ int scan[1024];

    // ---- Phase 1: ordered compaction of valid detections ----
    const int PER = NDET / 1024;   // 8 contiguous per thread (keeps index order)
    int base = t * PER;
    int flags[PER];
    int cnt = 0;
    #pragma unroll
    for (int k = 0; k < PER; k++) { flags[k] = g_valid[base + k]; cnt += flags[k]; }
    scan[t] = cnt;
    __syncthreads();
    // Hillis-Steele inclusive scan
    for (int d = 1; d < 1024; d <<= 1) {
        int add = (t >= d) ? scan[t - d] : 0;
        __syncthreads();
        scan[t] += add;
        __syncthreads();
    }
    int off = scan[t] - cnt;        // exclusive prefix
    const int V = scan[1023];       // total valid
    #pragma unroll
    for (int k = 0; k < PER; k++) {
        if (flags[k]) {
            int i = base + k;
            c_conf[off] = g_conf[i];
            c_box[off]  = g_box[i];
            off++;
        }
    }
    __syncthreads();   // block-scope fence: c_* now visible

    // ---- Phase 2: stable rank sort (conf desc, index asc) ----
    // Compaction preserved index order, so j<i <=> orig_idx_j < orig_idx_i.
    for (int i = t; i < V; i += 1024) {
        float ci = c_conf[i];
        int r = 0;
        for (int j = 0; j < V; j++) {
            float cj = c_conf[j];
            r += (cj > ci) || (cj == ci && j < i);
        }
        s_conf[r] = ci;
        s_box[r]  = c_box[i];
    }
    __syncthreads();

    // ---- Phase 3: greedy sequential NMS ----
    __shared__ unsigned char keep[NDET];
    for (int i = t; i < V; i += 1024) keep[i] = 1;
    __syncthreads();
    for (int i = 0; i + 1 < V; i++) {
        if (keep[i]) {                       // uniform read of shared flag
            float4 bi = s_box[i];
            float areai = (bi.z - bi.x) * (bi.w - bi.y);   // exact in fp32
            for (int j = i + 1 + t; j < V; j += 1024) {
                if (keep[j]) {
                    float4 bj = s_box[j];
                    float iw = fmaxf(fminf(bi.z, bj.z) - fmaxf(bi.x, bj.x), 0.0f);
                    float ih = fmaxf(fminf(bi.w, bj.w) - fmaxf(bi.y, bj.y), 0.0f);
                    float inter = iw * ih;
                    float areaj = (bj.z - bj.x) * (bj.w - bj.y);
                    float uni = areai + areaj - inter;     // exact integers
                    float iou = __fdiv_rn(inter, fmaxf(uni, 1e-9f));  // IEEE, matches JAX
                    if (iou > 0.45f) keep[j] = 0;
                }
            }
        }
        __syncthreads();
    }

    // ---- Phase 4: scatter survivors (rest of out already zeroed) ----
    for (int i = t; i < V; i += 1024) {
        if (keep[i]) {
            float4 b = s_box[i];
            out[4 * i + 0] = b.x;
            out[4 * i + 1] = b.y;
            out[4 * i + 2] = b.z;
            out[4 * i + 3] = b.w;
            out[NDET * 4 + i] = s_conf[i];
        }
    }
}

extern "C" void kernel_launch(void* const* d_in, const int* in_sizes, int n_in,
                              void* d_out, int out_size) {
    const float* x = (const float*)d_in[0];      // (1, 8192, 85) fp32
    // d_in[1] = original_image (640,640,3): only its shape (640,640) matters.
    float* out = (float*)d_out;                  // 8192*4 boxes then 8192 scores
    prep_kernel<<<1024, 256>>>(x, out);          // 8192 warps
    nms_kernel<<<1, 1024>>>(out);
}

// round 3
// speedup vs baseline: 1.0523x; 1.0523x over previous
#include <cuda_runtime.h>

#define NDET 8192
#define ROW  85
#define IMG  640
#define CAP  512          // fast-path capacity (V ~ 77 with this distribution)
#define WORDS (CAP / 64)  // 8

// Global scratch (allocation-free rule). Fully rewritten per launch on the
// paths that use it -> deterministic across graph replays.
__device__ float  g_conf[NDET];
__device__ float4 g_box[NDET];
__device__ int    g_valid[NDET];
// slow-path (V > CAP) scratch only:
__device__ float  c_conf[NDET];
__device__ float4 c_box[NDET];
__device__ float  s_conf[NDET];
__device__ float4 s_box[NDET];

// ---------------------------------------------------------------------------
// Kernel 1: one warp per detection. Coalesced row loads, warp max-reduce over
// class scores, clamped xyxy + validity. Also zeroes the 40960-float output.
// ---------------------------------------------------------------------------
__global__ void __launch_bounds__(256) prep_kernel(const float* __restrict__ x,
                                                   float* __restrict__ out) {
    int gtid = blockIdx.x * blockDim.x + threadIdx.x;
    if (gtid < NDET * 5) out[gtid] = 0.0f;   // boxes (4*N) + scores (N)

    int det  = gtid >> 5;
    int lane = gtid & 31;
    if (det >= NDET) return;

    const float* row = x + (long)det * ROW;
    float v0 = row[lane];
    float v1 = row[lane + 32];
    float v2 = (lane < 21) ? row[lane + 64] : -1e30f;

    // max over class scores at positions 6..84 (class ids 1..79)
    float m = (lane >= 6) ? v0 : -1e30f;
    m = fmaxf(m, v1);
    m = fmaxf(m, v2);
    #pragma unroll
    for (int o = 16; o; o >>= 1)
        m = fmaxf(m, __shfl_xor_sync(0xffffffffu, m, o));

    float b0   = __shfl_sync(0xffffffffu, v0, 0);
    float b1   = __shfl_sync(0xffffffffu, v0, 1);
    float b2   = __shfl_sync(0xffffffffu, v0, 2);
    float b3   = __shfl_sync(0xffffffffu, v0, 3);
    float conf = __shfl_sync(0xffffffffu, v0, 4);
    float cls0 = __shfl_sync(0xffffffffu, v0, 5);

    if (lane == 0) {
        float cx = b0 * 640.0f, cy = b1 * 640.0f;
        float w  = b2 * 640.0f, h  = b3 * 640.0f;
        int valid = (conf > 0.25f) && (cls0 >= m) && ((w > 0.0f) || (h > 0.0f));

        float hw = truncf(w * 0.5f);
        float hh = truncf(h * 0.5f);
        int x1 = (int)(cx - hw);
        int y1 = (int)(cy - hh);
        int x2 = (int)(cx + hw);
        int y2 = (int)(cy + hh);
        x1 = x1 > 0 ? x1 : 0;
        y1 = y1 > 0 ? y1 : 0;
        x2 = x2 < IMG ? x2 : IMG;
        y2 = y2 < IMG ? y2 : IMG;

        g_valid[det] = valid;
        g_conf[det]  = conf;
        g_box[det]   = make_float4((float)x1, (float)y1, (float)x2, (float)y2);
    }
}

// ---------------------------------------------------------------------------
// Kernel 2: single block, 1024 threads (= 32 warps exactly).
//   Phase 1: warp-shuffle scan compaction (2 barriers total)
//   Fast path (V <= CAP): everything in shared; parallel V x V suppression
//     bitmatrix; single-thread greedy reduce over 64-bit words; scatter.
//   Slow path (V > CAP): global-memory algorithm (correct, rare).
// ---------------------------------------------------------------------------
__global__ void __launch_bounds__(1024) nms_kernel(float* __restrict__ out) {
    const int t    = threadIdx.x;
    const int lane = t & 31;
    const int wid  = t >> 5;

    __shared__ int   wsum[32];
    __shared__ float sx1[CAP], sy1[CAP], sx2[CAP], sy2[CAP], scf[CAP];
    __shared__ unsigned long long sup[CAP][WORDS];       // 32 KB
    __shared__ unsigned long long keepw[WORDS];

    // ---- Phase 1: counts + warp-shuffle scan ----
    const int PER = NDET / 1024;   // 8 contiguous per thread (index order kept)
    int base = t * PER;
    int flags[PER];
    int cnt = 0;
    #pragma unroll
    for (int k = 0; k < PER; k++) { flags[k] = g_valid[base + k]; cnt += flags[k]; }

    int v = cnt;                   // inclusive scan within warp
    #pragma unroll
    for (int o = 1; o < 32; o <<= 1) {
        int n = __shfl_up_sync(0xffffffffu, v, o);
        if (lane >= o) v += n;
    }
    if (lane == 31) wsum[wid] = v;
    __syncthreads();
    if (wid == 0) {
        int s = wsum[lane];
        #pragma unroll
        for (int o = 1; o < 32; o <<= 1) {
            int n = __shfl_up_sync(0xffffffffu, s, o);
            if (lane >= o) s += n;
        }
        wsum[lane] = s;            // inclusive warp prefix
    }
    __syncthreads();
    const int V = wsum[31];
    int off = (wid > 0 ? wsum[wid - 1] : 0) + v - cnt;   // exclusive prefix

    if (V <= CAP) {
        // ================= FAST PATH (all shared) =================
        #pragma unroll
        for (int k = 0; k < PER; k++) {
            if (flags[k]) {
                int i = base + k;
                float4 b = g_box[i];
                scf[off] = g_conf[i];
                sx1[off] = b.x; sy1[off] = b.y; sx2[off] = b.z; sy2[off] = b.w;
                off++;
            }
        }
        __syncthreads();

        // ---- Phase 2: stable rank sort, in-place permute (1 elem/thread) ----
        float mx1 = 0, my1 = 0, mx2 = 0, my2 = 0, mcf = 0;
        int r = 0;
        if (t < V) {
            mcf = scf[t];
            mx1 = sx1[t]; my1 = sy1[t]; mx2 = sx2[t]; my2 = sy2[t];
            for (int j = 0; j < V; j++) {                 // broadcast reads
                float cj = scf[j];
                r += (cj > mcf) || (cj == mcf && j < t);
            }
        }
        __syncthreads();
        if (t < V) {
            scf[r] = mcf;
            sx1[r] = mx1; sy1[r] = my1; sx2[r] = mx2; sy2[r] = my2;
        }
        __syncthreads();

        // ---- Phase 3a: parallel suppression bit-matrix (row per thread) ----
        const int nw = (V + 63) >> 6;
        for (int i = t; i < V; i += 1024) {
            float x1i = sx1[i], y1i = sy1[i], x2i = sx2[i], y2i = sy2[i];
            float areai = (x2i - x1i) * (y2i - y1i);      // exact in fp32
            for (int w = 0; w < nw; w++) {
                unsigned long long bits = 0ull;
                int j0 = w << 6;
                int jend = min(j0 + 64, V);
                for (int j = (j0 > i + 1 ? j0 : i + 1); j < jend; j++) {
                    float iw = fmaxf(fminf(x2i, sx2[j]) - fmaxf(x1i, sx1[j]), 0.0f);
                    float ih = fmaxf(fminf(y2i, sy2[j]) - fmaxf(y1i, sy1[j]), 0.0f);
                    float inter = iw * ih;
                    float areaj = (sx2[j] - sx1[j]) * (sy2[j] - sy1[j]);
                    float uni = areai + areaj - inter;
                    float iou = __fdiv_rn(inter, fmaxf(uni, 1e-9f));
                    if (iou > 0.45f) bits |= 1ull << (j - j0);
                }
                sup[i][w] = bits;
            }
        }
        __syncthreads();

        // ---- Phase 3b: greedy reduce (single thread, registers + shared) ----
        if (t == 0) {
            unsigned long long kw[WORDS];
            #pragma unroll
            for (int w = 0; w < WORDS; w++) kw[w] = ~0ull;
            for (int i = 0; i < V; i++) {
                if ((kw[i >> 6] >> (i & 63)) & 1ull) {
                    for (int w = (i >> 6); w < nw; w++) kw[w] &= ~sup[i][w];
                }
            }
            #pragma unroll
            for (int w = 0; w < WORDS; w++) keepw[w] = kw[w];
        }
        __syncthreads();

        // ---- Phase 4: scatter survivors (rest of out already zeroed) ----
        if (t < V && ((keepw[t >> 6] >> (t & 63)) & 1ull)) {
            out[4 * t + 0] = sx1[t];
            out[4 * t + 1] = sy1[t];
            out[4 * t + 2] = sx2[t];
            out[4 * t + 3] = sy2[t];
            out[NDET * 4 + t] = scf[t];
        }
    } else {
        // ================= SLOW PATH (V > CAP; global arrays) =================
        #pragma unroll
        for (int k = 0; k < PER; k++) {
            if (flags[k]) {
                int i = base + k;
                c_conf[off] = g_conf[i];
                c_box[off]  = g_box[i];
                off++;
            }
        }
        __syncthreads();

        for (int i = t; i < V; i += 1024) {
            float ci = c_conf[i];
            int r = 0;
            for (int j = 0; j < V; j++) {
                float cj = c_conf[j];
                r += (cj > ci) || (cj == ci && j < i);
            }
            s_conf[r] = ci;
            s_box[r]  = c_box[i];
        }
        __syncthreads();

        unsigned char* keep = (unsigned char*)&sup[0][0];  // 32KB >= 8192
        for (int i = t; i < NDET; i += 1024) keep[i] = 1;
        __syncthreads();
        for (int i = 0; i + 1 < V; i++) {
            if (keep[i]) {
                float4 bi = s_box[i];
                float areai = (bi.z - bi.x) * (bi.w - bi.y);
                for (int j = i + 1 + t; j < V; j += 1024) {
                    if (keep[j]) {
                        float4 bj = s_box[j];
                        float iw = fmaxf(fminf(bi.z, bj.z) - fmaxf(bi.x, bj.x), 0.0f);
                        float ih = fmaxf(fminf(bi.w, bj.w) - fmaxf(bi.y, bj.y), 0.0f);
                        float inter = iw * ih;
                        float areaj = (bj.z - bj.x) * (bj.w - bj.y);
                        float uni = areai + areaj - inter;
                        float iou = __fdiv_rn(inter, fmaxf(uni, 1e-9f));
                        if (iou > 0.45f) keep[j] = 0;
                    }
                }
            }
            __syncthreads();
        }
        for (int i = t; i < V; i += 1024) {
            if (keep[i]) {
                float4 b = s_box[i];
                out[4 * i + 0] = b.x;
                out[4 * i + 1] = b.y;
                out[4 * i + 2] = b.z;
                out[4 * i + 3] = b.w;
                out[NDET * 4 + i] = s_conf[i];
            }
        }
    }
}

extern "C" void kernel_launch(void* const* d_in, const int* in_sizes, int n_in,
                              void* d_out, int out_size) {
    const float* x = (const float*)d_in[0];   // (1, 8192, 85) fp32
    float* out = (float*)d_out;               // 8192*4 boxes then 8192 scores
    prep_kernel<<<1024, 256>>>(x, out);
    nms_kernel<<<1, 1024>>>(out);
}

// round 6
// speedup vs baseline: 2.5675x; 2.4400x over previous
#include <cuda_runtime.h>

#define NDET 8192
#define ROW  85
#define IMG  640
#define CAP  512           // fast-path capacity (V ~ 77 expected)
#define W32  16            // 512/32 words per suppression row

// Global scratch (allocation-free rule). g_cnt: zero-init by module load,
// reset to 0 at the end of every nms -> invariant holds across graph replays.
__device__ int    g_cnt = 0;
__device__ float  c_conf[NDET];
__device__ float4 c_box[NDET];
__device__ int    c_idx[NDET];
// slow-path (V > CAP) scratch only:
__device__ float  s_conf[NDET];
__device__ float4 s_box[NDET];

// ---------------------------------------------------------------------------
// Kernel 1: one warp per detection. Coalesced row loads, warp max-reduce over
// class scores, clamped xyxy + validity. Valid dets are compacted directly via
// a global atomic counter (order restored canonically in nms). Also zeroes out.
// ---------------------------------------------------------------------------
__global__ void __launch_bounds__(256) prep_kernel(const float* __restrict__ x,
                                                   float* __restrict__ out) {
    int gtid = blockIdx.x * blockDim.x + threadIdx.x;
    if (gtid < NDET * 5) out[gtid] = 0.0f;   // boxes (4*N) + scores (N)

    int det  = gtid >> 5;
    int lane = gtid & 31;
    if (det >= NDET) return;

    const float* row = x + (long)det * ROW;
    float v0 = row[lane];
    float v1 = row[lane + 32];
    float v2 = (lane < 21) ? row[lane + 64] : -1e30f;

    // max over class scores at positions 6..84 (class ids 1..79)
    float m = (lane >= 6) ? v0 : -1e30f;
    m = fmaxf(m, v1);
    m = fmaxf(m, v2);
    #pragma unroll
    for (int o = 16; o; o >>= 1)
        m = fmaxf(m, __shfl_xor_sync(0xffffffffu, m, o));

    float b0   = __shfl_sync(0xffffffffu, v0, 0);
    float b1   = __shfl_sync(0xffffffffu, v0, 1);
    float b2   = __shfl_sync(0xffffffffu, v0, 2);
    float b3   = __shfl_sync(0xffffffffu, v0, 3);
    float conf = __shfl_sync(0xffffffffu, v0, 4);
    float cls0 = __shfl_sync(0xffffffffu, v0, 5);

    if (lane == 0) {
        float cx = b0 * 640.0f, cy = b1 * 640.0f;
        float w  = b2 * 640.0f, h  = b3 * 640.0f;
        // argmax==0  <=>  no later class strictly greater than cls0
        if ((conf > 0.25f) && (cls0 >= m) && ((w > 0.0f) || (h > 0.0f))) {
            float hw = truncf(w * 0.5f);
            float hh = truncf(h * 0.5f);
            int x1 = (int)(cx - hw);
            int y1 = (int)(cy - hh);
            int x2 = (int)(cx + hw);
            int y2 = (int)(cy + hh);
            x1 = x1 > 0 ? x1 : 0;
            y1 = y1 > 0 ? y1 : 0;
            x2 = x2 < IMG ? x2 : IMG;
            y2 = y2 < IMG ? y2 : IMG;
            int slot = atomicAdd(&g_cnt, 1);
            c_conf[slot] = conf;
            c_idx[slot]  = det;
            c_box[slot]  = make_float4((float)x1, (float)y1, (float)x2, (float)y2);
        }
    }
}

// ---------------------------------------------------------------------------
// Kernel 2: single block, 1024 threads.
//   Fast path (V <= CAP):
//     - load V compacted entries, build 64-bit sort keys (conf desc, idx asc)
//     - O(V^2) rank sort, 1 LDS/comparison, unrolled
//     - pair-parallel suppression matrix (independent IoUs -> MLP) w/ atomicOr
//     - warp-0 branchless greedy over register kw words (1 shfl + 1 LDS /iter)
//     - scatter survivors
//   Slow path (V > CAP): global-memory algorithm (correct, never hit here).
// ---------------------------------------------------------------------------
__global__ void __launch_bounds__(1024) nms_kernel(float* __restrict__ out) {
    const int t    = threadIdx.x;
    const int lane = t & 31;
    const int wid  = t >> 5;

    __shared__ float sx1[CAP], sy1[CAP], sx2[CAP], sy2[CAP], scf[CAP];
    __shared__ unsigned long long skey[CAP];
    __shared__ unsigned int sup[CAP * W32];     // 32 KB suppression bitmatrix
    __shared__ unsigned int keepw[W32];

    const int V = g_cnt;

    if (V <= CAP) {
        // ---- load + key build + zero matrix rows ----
        float mcf = 0, mx1 = 0, my1 = 0, mx2 = 0, my2 = 0;
        unsigned long long mykey = 0;
        if (t < V) {
            float4 b = c_box[t];
            mcf = c_conf[t];
            int idx = c_idx[t];
            mx1 = b.x; my1 = b.y; mx2 = b.z; my2 = b.w;
            mykey = ((unsigned long long)__float_as_uint(mcf) << 32)
                  | (unsigned int)(~idx);
            skey[t] = mykey;
        }
        for (int k = t; k < V * W32; k += 1024) sup[k] = 0u;
        __syncthreads();

        // ---- rank sort (stable: conf desc, original idx asc) ----
        int r = 0;
        if (t < V) {
            int j = 0;
            for (; j + 4 <= V; j += 4) {
                r += (skey[j]     > mykey);
                r += (skey[j + 1] > mykey);
                r += (skey[j + 2] > mykey);
                r += (skey[j + 3] > mykey);
            }
            for (; j < V; j++) r += (skey[j] > mykey);
            sx1[r] = mx1; sy1[r] = my1; sx2[r] = mx2; sy2[r] = my2; scf[r] = mcf;
        }
        __syncthreads();

        // ---- pair-parallel suppression matrix ----
        const int P = V * V;
        for (int p = t; p < P; p += 1024) {
            int i = p / V;
            int j = p - i * V;
            if (j > i) {
                float x1i = sx1[i], y1i = sy1[i], x2i = sx2[i], y2i = sy2[i];
                float x1j = sx1[j], y1j = sy1[j], x2j = sx2[j], y2j = sy2[j];
                float iw = fmaxf(fminf(x2i, x2j) - fmaxf(x1i, x1j), 0.0f);
                float ih = fmaxf(fminf(y2i, y2j) - fmaxf(y1i, y1j), 0.0f);
                float inter = iw * ih;
                float areai = (x2i - x1i) * (y2i - y1i);   // exact in fp32
                float areaj = (x2j - x1j) * (y2j - y1j);
                float uni = areai + areaj - inter;
                float iou = __fdiv_rn(inter, fmaxf(uni, 1e-9f)); // IEEE, matches JAX
                if (iou > 0.45f)
                    atomicOr(&sup[i * W32 + (j >> 5)], 1u << (j & 31));
            }
        }
        __syncthreads();

        // ---- warp-0 branchless greedy: kw word per lane ----
        if (wid == 0) {
            unsigned int kw = 0xFFFFFFFFu;      // lane w keeps bits [32w,32w+32)
            for (int i = 0; i < V; i++) {
                unsigned int row = (lane < W32) ? sup[i * W32 + lane] : 0u;
                unsigned int wi = __shfl_sync(0xffffffffu, kw, i >> 5);
                unsigned int alive = (wi >> (i & 31)) & 1u;
                kw &= ~(row & (0u - alive));
            }
            if (lane < W32) keepw[lane] = kw;
        }
        __syncthreads();

        // ---- scatter survivors (rest of out already zeroed by prep) ----
        if (t < V && ((keepw[t >> 5] >> (t & 31)) & 1u)) {
            out[4 * t + 0] = sx1[t];
            out[4 * t + 1] = sy1[t];
            out[4 * t + 2] = sx2[t];
            out[4 * t + 3] = sy2[t];
            out[NDET * 4 + t] = scf[t];
        }
        if (t == 0) g_cnt = 0;    // reset for next graph replay
    } else {
        // ================= SLOW PATH (V > CAP; global arrays) =================
        for (int i = t; i < V; i += 1024) {
            float ci = c_conf[i];
            int  ii  = c_idx[i];
            int r = 0;
            for (int j = 0; j < V; j++) {
                float cj = c_conf[j];
                r += (cj > ci) || (cj == ci && c_idx[j] < ii);
            }
            s_conf[r] = ci;
            s_box[r]  = c_box[i];
        }
        __syncthreads();

        unsigned char* keep = (unsigned char*)&sup[0];   // 32KB >= 8192
        for (int i = t; i < NDET; i += 1024) keep[i] = 1;
        __syncthreads();
        for (int i = 0; i + 1 < V; i++) {
            if (keep[i]) {
                float4 bi = s_box[i];
                float areai = (bi.z - bi.x) * (bi.w - bi.y);
                for (int j = i + 1 + t; j < V; j += 1024) {
                    if (keep[j]) {
                        float4 bj = s_box[j];
                        float iw = fmaxf(fminf(bi.z, bj.z) - fmaxf(bi.x, bj.x), 0.0f);
                        float ih = fmaxf(fminf(bi.w, bj.w) - fmaxf(bi.y, bj.y), 0.0f);
                        float inter = iw * ih;
                        float areaj = (bj.z - bj.x) * (bj.w - bj.y);
                        float uni = areai + areaj - inter;
                        float iou = __fdiv_rn(inter, fmaxf(uni, 1e-9f));
                        if (iou > 0.45f) keep[j] = 0;
                    }
                }
            }
            __syncthreads();
        }
        for (int i = t; i < V; i += 1024) {
            if (keep[i]) {
                float4 b = s_box[i];
                out[4 * i + 0] = b.x;
                out[4 * i + 1] = b.y;
                out[4 * i + 2] = b.z;
                out[4 * i + 3] = b.w;
                out[NDET * 4 + i] = s_conf[i];
            }
        }
        if (t == 0) g_cnt = 0;
    }
}

extern "C" void kernel_launch(void* const* d_in, const int* in_sizes, int n_in,
                              void* d_out, int out_size) {
    const float* x = (const float*)d_in[0];   // (1, 8192, 85) fp32
    float* out = (float*)d_out;               // 8192*4 boxes then 8192 scores
    prep_kernel<<<1024, 256>>>(x, out);
    nms_kernel<<<1, 1024>>>(out);
}